// round 1
// baseline (speedup 1.0000x reference)
#include <cuda_runtime.h>
#include <cstddef>

// ---------------------------------------------------------------------------
// Problem constants
//   x:        [16, 64, 30, 64, 44] fp32
//   w_reduce: [16, 64], b_reduce: [16]
//   w_fc1:    [128, 16], b_fc1: [128]
//   w_fc2:    [128, 864, 1]  (grouped 1x1 conv weights)
//   out:      [16, 64, 30, 64, 44] fp32
// ---------------------------------------------------------------------------
#define B_   16
#define C_   64     // INP == OUP
#define T_   30
#define H_   64
#define W_   44
#define SPAT (T_ * H_ * W_)        // 84480
#define CH_STRIDE SPAT
#define TH_STRIDE (H_ * W_)        // 2816

// Scratch (static device globals; no allocation)
__device__ float d_gap[B_ * C_];                       // GAP result [16,64]
__device__ float d_h[B_ * 128];                        // sigmoid activations [16,128]
__device__ float d_wdyn[B_ * C_ * C_ * 28];            // padded weights [b][oc][ic][28] (27 taps + pad)

// ---------------------------------------------------------------------------
// Kernel 1: global average pool over T,H,W for each (b,c). 1024 blocks.
// ---------------------------------------------------------------------------
__global__ void gap_kernel(const float* __restrict__ x) {
    const int bc = blockIdx.x;                       // 0..1023
    const float4* xp = reinterpret_cast<const float4*>(x) + (size_t)bc * (SPAT / 4);
    float s = 0.f;
    for (int i = threadIdx.x; i < SPAT / 4; i += 256) {
        float4 v = xp[i];
        s += (v.x + v.y) + (v.z + v.w);
    }
    // warp reduce
    #pragma unroll
    for (int o = 16; o > 0; o >>= 1) s += __shfl_xor_sync(0xffffffffu, s, o);
    __shared__ float red[8];
    if ((threadIdx.x & 31) == 0) red[threadIdx.x >> 5] = s;
    __syncthreads();
    if (threadIdx.x < 8) {
        float v = red[threadIdx.x];
        #pragma unroll
        for (int o = 4; o > 0; o >>= 1) v += __shfl_xor_sync(0xffu, v, o);
        if (threadIdx.x == 0) d_gap[bc] = v * (1.0f / (float)SPAT);
    }
}

// ---------------------------------------------------------------------------
// Kernel 2: reduce FC (64->16) + fc1 (16->128) + sigmoid. Single block.
// ---------------------------------------------------------------------------
__global__ void fc_kernel(const float* __restrict__ w_reduce,
                          const float* __restrict__ b_reduce,
                          const float* __restrict__ w_fc1,
                          const float* __restrict__ b_fc1) {
    __shared__ float sg[B_ * 16];
    const int tid = threadIdx.x;
    if (tid < B_ * 16) {
        int b = tid >> 4, j = tid & 15;
        float s = b_reduce[j];
        #pragma unroll 4
        for (int i = 0; i < 64; i++) s += d_gap[b * 64 + i] * w_reduce[j * 64 + i];
        sg[b * 16 + j] = s;
    }
    __syncthreads();
    for (int idx = tid; idx < B_ * 128; idx += 256) {
        int b = idx >> 7, c = idx & 127;
        float s = b_fc1[c];
        #pragma unroll
        for (int i = 0; i < 16; i++) s += sg[b * 16 + i] * w_fc1[c * 16 + i];
        d_h[idx] = 1.0f / (1.0f + expf(-s));
    }
}

// ---------------------------------------------------------------------------
// Kernel 3: dynamic weight generation.
//   wdyn[b, g, o] = w_fc2[g, o] * h[b, g]   (g = r/864, r = oc*1728 + ic*27 + tap)
// stored padded as d_wdyn[((b*64+oc)*64+ic)*28 + tap]
// ---------------------------------------------------------------------------
__global__ void wdyn_kernel(const float* __restrict__ w_fc2) {
    int idx = blockIdx.x * blockDim.x + threadIdx.x;
    const int total = B_ * C_ * C_ * 27;  // 1,769,472
    if (idx >= total) return;
    int b = idx / (C_ * C_ * 27);
    int r = idx - b * (C_ * C_ * 27);     // oc*1728 + ic*27 + tap
    int g = r / 864;
    float v = w_fc2[r] * d_h[b * 128 + g];
    int oc  = r / 1728;
    int rem = r - oc * 1728;
    int ic  = rem / 27;
    int tap = rem - ic * 27;
    d_wdyn[((size_t)((b * C_ + oc) * C_) + ic) * 28 + tap] = v;
}

// ---------------------------------------------------------------------------
// Kernel 4: per-sample conv3d 3x3x3, pad 1.
// Block = (b, t, 4-row h tile); 512 threads = 64 oc x 4 h x 2 w-halves.
// Each thread: 22 contiguous w outputs, fp32 accumulators.
// x staged in smem in 8-input-channel chunks; weights via LDG.128 from L2.
// ---------------------------------------------------------------------------
#define ICCHUNK 8
#define SLAB (ICCHUNK * 3 * 6 * 46)   // 6624 floats, 26.5 KB

__global__ void __launch_bounds__(512, 1)
conv_kernel(const float* __restrict__ x, float* __restrict__ out) {
    __shared__ float xs[SLAB];

    const int b  = blockIdx.y;
    const int t  = blockIdx.x >> 4;
    const int h0 = (blockIdx.x & 15) << 2;
    const int tid = threadIdx.x;
    const int oc = tid >> 3;
    const int hh = (tid >> 1) & 3;
    const int ws = tid & 1;

    float acc[22];
    #pragma unroll
    for (int k = 0; k < 22; k++) acc[k] = 0.f;

    const float* xb = x + (size_t)b * (C_ * SPAT);
    const float4* wp4 = reinterpret_cast<const float4*>(
        d_wdyn + ((size_t)(b * C_ + oc) * C_) * 28);

    #pragma unroll 1
    for (int ic0 = 0; ic0 < C_; ic0 += ICCHUNK) {
        __syncthreads();   // previous compute done before overwriting xs
        // cooperative slab load: [icchunk][dt:3][hrow:6][w2:46]
        #pragma unroll 1
        for (int j = tid; j < SLAB; j += 512) {
            int w2   = j % 46;
            int r    = j / 46;
            int hrow = r % 6;
            int r2   = r / 6;
            int dt   = r2 % 3;
            int ic   = r2 / 3;
            int gt = t + dt - 1;
            int gh = h0 + hrow - 1;
            int gw = w2 - 1;
            float v = 0.f;
            if (((unsigned)gt < (unsigned)T_) & ((unsigned)gh < (unsigned)H_) &
                ((unsigned)gw < (unsigned)W_))
                v = __ldg(&xb[((size_t)(ic0 + ic) * T_ + gt) * TH_STRIDE + gh * W_ + gw]);
            xs[j] = v;
        }
        __syncthreads();

        #pragma unroll 1
        for (int ic = 0; ic < ICCHUNK; ic++) {
            // 27 taps for (oc, ic0+ic) -> registers via 7x float4
            float wreg[28];
            #pragma unroll
            for (int q = 0; q < 7; q++) {
                float4 v = wp4[(ic0 + ic) * 7 + q];
                wreg[q * 4 + 0] = v.x; wreg[q * 4 + 1] = v.y;
                wreg[q * 4 + 2] = v.z; wreg[q * 4 + 3] = v.w;
            }
            #pragma unroll
            for (int dt = 0; dt < 3; dt++) {
                #pragma unroll
                for (int dh = 0; dh < 3; dh++) {
                    const float* xr = &xs[((ic * 3 + dt) * 6 + hh + dh) * 46 + ws * 22];
                    const float w0 = wreg[(dt * 3 + dh) * 3 + 0];
                    const float w1 = wreg[(dt * 3 + dh) * 3 + 1];
                    const float w2 = wreg[(dt * 3 + dh) * 3 + 2];
                    float x0 = xr[0], x1 = xr[1];
                    #pragma unroll
                    for (int k = 0; k < 22; k++) {
                        float x2 = xr[k + 2];
                        acc[k] = fmaf(w0, x0, acc[k]);
                        acc[k] = fmaf(w1, x1, acc[k]);
                        acc[k] = fmaf(w2, x2, acc[k]);
                        x0 = x1; x1 = x2;
                    }
                }
            }
        }
    }

    float* op = out + (((size_t)(b * C_ + oc) * T_ + t) * H_ + (h0 + hh)) * W_ + ws * 22;
    #pragma unroll
    for (int k = 0; k < 22; k++) op[k] = acc[k];
}

// ---------------------------------------------------------------------------
extern "C" void kernel_launch(void* const* d_in, const int* in_sizes, int n_in,
                              void* d_out, int out_size) {
    const float* x        = (const float*)d_in[0];
    const float* w_reduce = (const float*)d_in[1];
    const float* b_reduce = (const float*)d_in[2];
    const float* w_fc1    = (const float*)d_in[3];
    const float* b_fc1    = (const float*)d_in[4];
    const float* w_fc2    = (const float*)d_in[5];
    float* out = (float*)d_out;

    gap_kernel<<<B_ * C_, 256>>>(x);
    fc_kernel<<<1, 256>>>(w_reduce, b_reduce, w_fc1, b_fc1);
    {
        const int total = B_ * C_ * C_ * 27;
        wdyn_kernel<<<(total + 255) / 256, 256>>>(w_fc2);
    }
    {
        dim3 grid(T_ * (H_ / 4), B_);   // (480, 16)
        conv_kernel<<<grid, 512>>>(x, out);
    }
}

// round 2
// speedup vs baseline: 1.3538x; 1.3538x over previous
#include <cuda_runtime.h>
#include <cstddef>

// ---------------------------------------------------------------------------
// Problem constants
//   x:        [16, 64, 30, 64, 44] fp32
//   w_reduce: [16, 64], b_reduce: [16]
//   w_fc1:    [128, 16], b_fc1: [128]
//   w_fc2:    [128, 864, 1]
//   out:      [16, 64, 30, 64, 44] fp32
// ---------------------------------------------------------------------------
#define B_   16
#define C_   64
#define T_   30
#define H_   64
#define W_   44
#define SPAT (T_ * H_ * W_)        // 84480
#define TH_STRIDE (H_ * W_)        // 2816

typedef unsigned long long ull;

// Scratch (static device globals; no allocation)
__device__ float d_gap[B_ * C_];
__device__ float d_h[B_ * 128];
// packed duplicated weights: [b][oc][ic][dt][10] u64, element k (0..8) = (w,w)
__device__ ull d_wdyn2[B_ * C_ * C_ * 3 * 10];

__device__ __forceinline__ ull pack2(float lo, float hi) {
    return (ull)__float_as_uint(lo) | ((ull)__float_as_uint(hi) << 32);
}
__device__ __forceinline__ ull fma2(ull a, ull b, ull c) {
    ull d;
    asm("fma.rn.f32x2 %0, %1, %2, %3;" : "=l"(d) : "l"(a), "l"(b), "l"(c));
    return d;
}

// ---------------------------------------------------------------------------
// Kernel 1: global average pool over T,H,W for each (b,c). 1024 blocks.
// ---------------------------------------------------------------------------
__global__ void gap_kernel(const float* __restrict__ x) {
    const int bc = blockIdx.x;
    const float4* xp = reinterpret_cast<const float4*>(x) + (size_t)bc * (SPAT / 4);
    float s = 0.f;
    for (int i = threadIdx.x; i < SPAT / 4; i += 256) {
        float4 v = xp[i];
        s += (v.x + v.y) + (v.z + v.w);
    }
    #pragma unroll
    for (int o = 16; o > 0; o >>= 1) s += __shfl_xor_sync(0xffffffffu, s, o);
    __shared__ float red[8];
    if ((threadIdx.x & 31) == 0) red[threadIdx.x >> 5] = s;
    __syncthreads();
    if (threadIdx.x < 8) {
        float v = red[threadIdx.x];
        #pragma unroll
        for (int o = 4; o > 0; o >>= 1) v += __shfl_xor_sync(0xffu, v, o);
        if (threadIdx.x == 0) d_gap[bc] = v * (1.0f / (float)SPAT);
    }
}

// ---------------------------------------------------------------------------
// Kernel 2: reduce FC (64->16) + fc1 (16->128) + sigmoid. Single block.
// ---------------------------------------------------------------------------
__global__ void fc_kernel(const float* __restrict__ w_reduce,
                          const float* __restrict__ b_reduce,
                          const float* __restrict__ w_fc1,
                          const float* __restrict__ b_fc1) {
    __shared__ float sg[B_ * 16];
    const int tid = threadIdx.x;
    if (tid < B_ * 16) {
        int b = tid >> 4, j = tid & 15;
        float s = b_reduce[j];
        #pragma unroll 4
        for (int i = 0; i < 64; i++) s += d_gap[b * 64 + i] * w_reduce[j * 64 + i];
        sg[b * 16 + j] = s;
    }
    __syncthreads();
    for (int idx = tid; idx < B_ * 128; idx += 256) {
        int b = idx >> 7, c = idx & 127;
        float s = b_fc1[c];
        #pragma unroll
        for (int i = 0; i < 16; i++) s += sg[b * 16 + i] * w_fc1[c * 16 + i];
        d_h[idx] = 1.0f / (1.0f + expf(-s));
    }
}

// ---------------------------------------------------------------------------
// Kernel 3: dynamic weight generation into duplicated-packed padded layout.
//   r = oc*1728 + ic*27 + tap;  tap = dt*9 + k
//   d_wdyn2[(((b*64+oc)*64+ic)*3+dt)*10 + k] = (v, v)
// ---------------------------------------------------------------------------
__global__ void wdyn_kernel(const float* __restrict__ w_fc2) {
    int idx = blockIdx.x * blockDim.x + threadIdx.x;
    const int total = B_ * C_ * C_ * 27;
    if (idx >= total) return;
    int b = idx / (C_ * C_ * 27);
    int r = idx - b * (C_ * C_ * 27);
    int g = r / 864;
    float v = w_fc2[r] * d_h[b * 128 + g];
    int oc  = r / 1728;
    int rem = r - oc * 1728;
    int ic  = rem / 27;
    int tap = rem - ic * 27;
    int dt  = tap / 9;
    int k   = tap - dt * 9;
    d_wdyn2[(size_t)(((b * C_ + oc) * C_ + ic) * 3 + dt) * 10 + k] = pack2(v, v);
}

// ---------------------------------------------------------------------------
// Kernel 4: per-sample conv3d 3x3x3, pad 1, fp32x2 packed along t.
//
// Block = (b, t-pair, h-pair): outputs 2t x 2h x 44w x 64oc.
// 384 threads = 64 oc x 6 ws; thread = 2t x 2h x 8w = 16 packed accumulators.
//
// smem x slab (per ic in chunk of 4):
//   [pp:3][row:4][ws:6][jj:12] u64, window ws at byte offset ws*144 (stagger
//   => each warp LDS.128 hits 6 distinct 16B sectors in 128B -> 1 wavefront).
//   u64 element = (x[t0-1+pp], x[t0+pp]) at (h0-1+row, ws*8+jj-2).
// ---------------------------------------------------------------------------
#define ICCHUNK 4
#define WINU 18                       // u64 stride per ws window (12 used + 6 pad)
#define ROWU (6 * WINU)               // 108 u64 per (pp,row)
#define ICU  (3 * 4 * ROWU)           // 1296 u64 per ic
#define SLABU (ICCHUNK * ICU)         // 5184 u64 = 41.5 KB

__global__ void __launch_bounds__(384, 1)
conv_kernel(const float* __restrict__ x, float* __restrict__ out) {
    __shared__ __align__(16) ull xs[SLABU];

    const int b  = blockIdx.y;
    const int tp = blockIdx.x >> 5;        // 0..14
    const int hq = blockIdx.x & 31;        // 0..31
    const int t0 = tp * 2;
    const int h0 = hq * 2;
    const int tid = threadIdx.x;
    const int oc = tid / 6;
    const int ws = tid - oc * 6;

    ull acc[16];
    #pragma unroll
    for (int k = 0; k < 16; k++) acc[k] = 0ull;

    const float* xb = x + (size_t)b * (C_ * SPAT);
    const ull* wbase = d_wdyn2 + (size_t)((b * C_ + oc) * C_) * 30;

    #pragma unroll 1
    for (int ic0 = 0; ic0 < C_; ic0 += ICCHUNK) {
        __syncthreads();
        // ---- cooperative slab fill: 3456 logical u64, 9 iters of 384 ----
        #pragma unroll 1
        for (int it = 0; it < 9; it++) {
            int i  = tid + it * 384;
            int jj = i % 12;  int q = i / 12;
            int w6 = q % 6;   q /= 6;
            int r  = q % 4;   q /= 4;
            int pp = q % 3;
            int ic = q / 3;
            int gw  = w6 * 8 + jj - 2;
            int gh  = h0 - 1 + r;
            int gtl = t0 - 1 + pp;
            float lo = 0.f, hi = 0.f;
            if (((unsigned)gh < (unsigned)H_) & ((unsigned)gw < (unsigned)W_)) {
                const float* base = xb + (size_t)(ic0 + ic) * SPAT + gh * W_ + gw;
                if ((unsigned)gtl < (unsigned)T_)       lo = __ldg(base + gtl * TH_STRIDE);
                if ((unsigned)(gtl + 1) < (unsigned)T_) hi = __ldg(base + (gtl + 1) * TH_STRIDE);
            }
            xs[(ic * 3 + pp) * (4 * ROWU) + r * ROWU + w6 * WINU + jj] = pack2(lo, hi);
        }
        __syncthreads();

        // ---- compute ----
        #pragma unroll 1
        for (int ic = 0; ic < ICCHUNK; ic++) {
            const ull* wp = wbase + (size_t)(ic0 + ic) * 30;
            #pragma unroll
            for (int dt = 0; dt < 3; dt++) {
                // 9 packed weights (4 LDG.128 + 1 LDG.64, L2-resident)
                ull wv[9];
                {
                    const ulonglong2* wq = reinterpret_cast<const ulonglong2*>(wp + dt * 10);
                    ulonglong2 a0 = wq[0], a1 = wq[1], a2 = wq[2], a3 = wq[3];
                    wv[0] = a0.x; wv[1] = a0.y; wv[2] = a1.x; wv[3] = a1.y;
                    wv[4] = a2.x; wv[5] = a2.y; wv[6] = a3.x; wv[7] = a3.y;
                    wv[8] = wp[dt * 10 + 8];
                }
                const ull* xrow0 = &xs[(ic * 3 + dt) * (4 * ROWU) + ws * WINU];
                #pragma unroll
                for (int r = 0; r < 4; r++) {
                    ull P[12];
                    {
                        const ulonglong2* pr =
                            reinterpret_cast<const ulonglong2*>(xrow0 + r * ROWU);
                        #pragma unroll
                        for (int k = 0; k < 6; k++) {
                            ulonglong2 v = pr[k];
                            P[2 * k] = v.x; P[2 * k + 1] = v.y;
                        }
                    }
                    #pragma unroll
                    for (int dh = 0; dh < 3; dh++) {
                        const int oh = r - dh;
                        if (oh == 0 || oh == 1) {
                            #pragma unroll
                            for (int dw = 0; dw < 3; dw++) {
                                const ull w = wv[dh * 3 + dw];
                                #pragma unroll
                                for (int owl = 0; owl < 8; owl++)
                                    acc[oh * 8 + owl] =
                                        fma2(w, P[owl + dw + 1], acc[oh * 8 + owl]);
                            }
                        }
                    }
                }
            }
        }
    }

    // ---- store: unpack t-pairs ----
    #pragma unroll
    for (int oh = 0; oh < 2; oh++) {
        int obase = ((b * C_ + oc) * T_ + t0) * TH_STRIDE + (h0 + oh) * W_;
        #pragma unroll
        for (int owl = 0; owl < 8; owl++) {
            int gw = ws * 8 + owl;
            if (gw < W_) {
                ull a = acc[oh * 8 + owl];
                out[obase + gw]             = __uint_as_float((unsigned)(a & 0xffffffffu));
                out[obase + TH_STRIDE + gw] = __uint_as_float((unsigned)(a >> 32));
            }
        }
    }
}

// ---------------------------------------------------------------------------
extern "C" void kernel_launch(void* const* d_in, const int* in_sizes, int n_in,
                              void* d_out, int out_size) {
    const float* x        = (const float*)d_in[0];
    const float* w_reduce = (const float*)d_in[1];
    const float* b_reduce = (const float*)d_in[2];
    const float* w_fc1    = (const float*)d_in[3];
    const float* b_fc1    = (const float*)d_in[4];
    const float* w_fc2    = (const float*)d_in[5];
    float* out = (float*)d_out;

    gap_kernel<<<B_ * C_, 256>>>(x);
    fc_kernel<<<1, 256>>>(w_reduce, b_reduce, w_fc1, b_fc1);
    {
        const int total = B_ * C_ * C_ * 27;
        wdyn_kernel<<<(total + 255) / 256, 256>>>(w_fc2);
    }
    {
        dim3 grid((T_ / 2) * (H_ / 2), B_);   // (480, 16)
        conv_kernel<<<grid, 384>>>(x, out);
    }
}

// round 4
// speedup vs baseline: 5.6393x; 4.1656x over previous
#include <cuda_runtime.h>
#include <cuda_bf16.h>
#include <cstdint>
#include <cstddef>

// ---------------------------------------------------------------------------
// Problem constants
//   x [16,64,30,64,44] f32 ; out same shape
// ---------------------------------------------------------------------------
#define B_   16
#define C_   64
#define T_   30
#define H_   64
#define W_   44
#define SPAT (T_ * H_ * W_)        // 84480
#define TH_STRIDE (H_ * W_)        // 2816

// conv tiling
#define HH 8                       // output h rows per block
#define HP 10                      // h rows incl halo
#define WP 48                      // padded w per row (44 valid)
#define ROWS (3 * HP * WP)         // 1440 pixel rows per slab
#define ROWSP 1456                 // padded row count
#define SLAB_BYTES (ROWSP * 32)    // 46592 per slab
#define SM_TOTAL (2 * SLAB_BYTES)  // 93184 (xh slab @0, xl slab @SLAB_BYTES)

// Scratch (static device globals; no allocation)
__device__ float d_gap[B_ * C_];
__device__ float d_h[B_ * 128];
// W fragments, mma-lane order: [b][g:4][tap:27][term:2][mt:4][lane:32] uint4
__device__ uint4 d_wfrag[B_ * 4 * 27 * 2 * 4 * 32];

// ---------------------------------------------------------------------------
// helpers
// ---------------------------------------------------------------------------
__device__ __forceinline__ unsigned smem_u32(const void* p) {
    unsigned a;
    asm("{ .reg .u64 t; cvta.to.shared.u64 t, %1; cvt.u32.u64 %0, t; }"
        : "=r"(a) : "l"(p));
    return a;
}
__device__ __forceinline__ void ldmx4(unsigned& r0, unsigned& r1,
                                      unsigned& r2, unsigned& r3, unsigned a) {
    asm volatile("ldmatrix.sync.aligned.m8n8.x4.shared.b16 {%0,%1,%2,%3}, [%4];"
                 : "=r"(r0), "=r"(r1), "=r"(r2), "=r"(r3) : "r"(a));
}
__device__ __forceinline__ void mma_bf16(float* c, const uint4 a,
                                         unsigned b0, unsigned b1) {
    asm volatile(
        "mma.sync.aligned.m16n8k16.row.col.f32.bf16.bf16.f32 "
        "{%0,%1,%2,%3}, {%4,%5,%6,%7}, {%8,%9}, {%0,%1,%2,%3};"
        : "+f"(c[0]), "+f"(c[1]), "+f"(c[2]), "+f"(c[3])
        : "r"(a.x), "r"(a.y), "r"(a.z), "r"(a.w), "r"(b0), "r"(b1));
}
__device__ __forceinline__ unsigned short bf_hi(float v) {
    return __bfloat16_as_ushort(__float2bfloat16_rn(v));
}
__device__ __forceinline__ unsigned short bf_lo(float v) {
    float hf = __bfloat162float(__float2bfloat16_rn(v));
    return __bfloat16_as_ushort(__float2bfloat16_rn(v - hf));
}

// ---------------------------------------------------------------------------
// Kernel 1: global average pool. 1024 blocks.
// ---------------------------------------------------------------------------
__global__ void gap_kernel(const float* __restrict__ x) {
    const int bc = blockIdx.x;
    const float4* xp = reinterpret_cast<const float4*>(x) + (size_t)bc * (SPAT / 4);
    float s = 0.f;
    for (int i = threadIdx.x; i < SPAT / 4; i += 256) {
        float4 v = xp[i];
        s += (v.x + v.y) + (v.z + v.w);
    }
    #pragma unroll
    for (int o = 16; o > 0; o >>= 1) s += __shfl_xor_sync(0xffffffffu, s, o);
    __shared__ float red[8];
    if ((threadIdx.x & 31) == 0) red[threadIdx.x >> 5] = s;
    __syncthreads();
    if (threadIdx.x < 8) {
        float v = red[threadIdx.x];
        #pragma unroll
        for (int o = 4; o > 0; o >>= 1) v += __shfl_xor_sync(0xffu, v, o);
        if (threadIdx.x == 0) d_gap[bc] = v * (1.0f / (float)SPAT);
    }
}

// ---------------------------------------------------------------------------
// Kernel 2: reduce FC + fc1 + sigmoid. Single block.
// ---------------------------------------------------------------------------
__global__ void fc_kernel(const float* __restrict__ w_reduce,
                          const float* __restrict__ b_reduce,
                          const float* __restrict__ w_fc1,
                          const float* __restrict__ b_fc1) {
    __shared__ float sg[B_ * 16];
    const int tid = threadIdx.x;
    if (tid < B_ * 16) {
        int b = tid >> 4, j = tid & 15;
        float s = b_reduce[j];
        #pragma unroll 4
        for (int i = 0; i < 64; i++) s += d_gap[b * 64 + i] * w_reduce[j * 64 + i];
        sg[b * 16 + j] = s;
    }
    __syncthreads();
    for (int idx = tid; idx < B_ * 128; idx += 256) {
        int b = idx >> 7, c = idx & 127;
        float s = b_fc1[c];
        #pragma unroll
        for (int i = 0; i < 16; i++) s += sg[b * 16 + i] * w_fc1[c * 16 + i];
        d_h[idx] = 1.0f / (1.0f + expf(-s));
    }
}

// ---------------------------------------------------------------------------
// Kernel 3: dynamic weights -> mma a-fragment layout (hi and lo terms).
// One thread per uint4 (= 4 a-regs = 8 bf16 weight values).
//   a-frag m16n8k16: reg r -> row = lane/4 + (r&1)*8, kcol = 2*(lane%3..)
// ---------------------------------------------------------------------------
__global__ void wdyn_kernel(const float* __restrict__ w_fc2) {
    const int idx = blockIdx.x * blockDim.x + threadIdx.x;
    const int total = B_ * 4 * 27 * 2 * 4 * 32;   // 442368
    if (idx >= total) return;
    const int lane = idx & 31;
    const int mt   = (idx >> 5) & 3;
    const int term = (idx >> 7) & 1;
    int q = idx >> 8;
    const int tap = q % 27;  q /= 27;
    const int g   = q & 3;
    const int b   = q >> 2;

    unsigned r32[4];
    #pragma unroll
    for (int r = 0; r < 4; r++) {
        const int row = (lane >> 2) + (r & 1) * 8;
        const int kb  = 2 * (lane & 3) + (r >> 1) * 8;
        const int oc  = mt * 16 + row;
        unsigned short e[2];
        #pragma unroll
        for (int j = 0; j < 2; j++) {
            const int ic = g * 16 + kb + j;
            const float v = w_fc2[oc * 1728 + ic * 27 + tap] *
                            d_h[b * 128 + oc * 2 + (ic >= 32 ? 1 : 0)];
            e[j] = term == 0 ? bf_hi(v) : bf_lo(v);
        }
        r32[r] = (unsigned)e[0] | ((unsigned)e[1] << 16);
    }
    d_wfrag[idx] = make_uint4(r32[0], r32[1], r32[2], r32[3]);
}

// ---------------------------------------------------------------------------
// Kernel 4: implicit-GEMM conv via mma.sync bf16 (3-term hi/lo split).
// Block = (t, hgroup of 8, b): 384 padded pixels x 64 oc.
// 8 warps, warp = m64(oc) x n48(pixels = one h row).
// K loop: 4 ic16 chunks x 27 taps; tap shift = smem row offset.
// ---------------------------------------------------------------------------
extern __shared__ char smem[];

__global__ void __launch_bounds__(256, 1)
conv_kernel(const float* __restrict__ x, float* __restrict__ out) {
    const int t  = blockIdx.x;
    const int h0 = blockIdx.y * HH;
    const int b  = blockIdx.z;
    const int tid = threadIdx.x;
    const int wid = tid >> 5;
    const int lane = tid & 31;

    const unsigned sb = smem_u32(smem);
    const unsigned sl_h = sb;
    const unsigned sl_l = sb + SLAB_BYTES;

    float acc[4][6][4];
    #pragma unroll
    for (int mt = 0; mt < 4; mt++)
        #pragma unroll
        for (int nt = 0; nt < 6; nt++)
            #pragma unroll
            for (int k = 0; k < 4; k++) acc[mt][nt][k] = 0.f;

    const float* xb = x + (size_t)b * (C_ * SPAT);
    // ldmatrix lane address components (B operand, col-major k16 x n8 pairs)
    const int rb_off = (lane & 7) + ((lane >> 4) & 1) * 8;  // row within 16-px group
    const int bhalf  = (lane >> 3) & 1;                     // 16B half (k 0-7 / 8-15)

    #pragma unroll 1
    for (int g = 0; g < 4; g++) {
        __syncthreads();
        // ---- fill xh/xl slabs: 1440 rows of 16 ic bf16 (32B), swizzled ----
        #pragma unroll 1
        for (int r = tid; r < ROWS; r += 256) {
            int t2 = r / (HP * WP);
            int rr = r - t2 * (HP * WP);
            int hp = rr / WP;
            int wp = rr - hp * WP;
            int gt = t + t2 - 1, gh = h0 + hp - 1, gw = wp - 1;
            unsigned hh[4] = {0, 0, 0, 0}, ll[4] = {0, 0, 0, 0};
            if (((unsigned)gt < (unsigned)T_) & ((unsigned)gh < (unsigned)H_) &
                ((unsigned)gw < (unsigned)W_)) {
                const float* p = xb + (size_t)(g * 16) * SPAT +
                                 (size_t)gt * TH_STRIDE + gh * W_ + gw;
                #pragma unroll
                for (int j = 0; j < 8; j++) {
                    float v0 = __ldg(p + (2 * j) * SPAT);
                    float v1 = __ldg(p + (2 * j + 1) * SPAT);
                    hh[j >> 1] |= ((unsigned)bf_hi(v0) | ((unsigned)bf_hi(v1) << 16))
                                  << 0;  // placed below
                    // overwrite properly (see packing below)
                }
                // repack cleanly: 16 values -> 4+4 u32
                #pragma unroll
                for (int q = 0; q < 4; q++) {
                    float a0 = __ldg(p + (4 * q + 0) * SPAT);
                    float a1 = __ldg(p + (4 * q + 1) * SPAT);
                    float a2 = __ldg(p + (4 * q + 2) * SPAT);
                    float a3 = __ldg(p + (4 * q + 3) * SPAT);
                    // two u32 per quad: (a0,a1), (a2,a3) -> indices 2q, 2q+1
                    unsigned u0 = (unsigned)bf_hi(a0) | ((unsigned)bf_hi(a1) << 16);
                    unsigned u1 = (unsigned)bf_hi(a2) | ((unsigned)bf_hi(a3) << 16);
                    unsigned w0 = (unsigned)bf_lo(a0) | ((unsigned)bf_lo(a1) << 16);
                    unsigned w1 = (unsigned)bf_lo(a2) | ((unsigned)bf_lo(a3) << 16);
                    if (q < 2) { hh[2 * q] = u0; hh[2 * q + 1] = u1;
                                 ll[2 * q] = w0; ll[2 * q + 1] = w1; }
                    else       { hh[2 * (q - 2)] = (q == 2 && false) ? 0 : hh[2 * (q - 2)];
                                 // second half handled below
                    }
                    if (q >= 2) {
                        // store second 16B half directly here
                        unsigned off2 = r * 32 + ((((r >> 2) & 1) ^ 1) << 4) +
                                        (q - 2) * 8;
                        *(uint2*)(smem + (off2)) = make_uint2(u0, u1);
                        *(uint2*)(smem + SLAB_BYTES + off2) = make_uint2(w0, w1);
                    }
                }
            } else {
                // zero both halves
                unsigned off2 = r * 32 + ((((r >> 2) & 1) ^ 1) << 4);
                *(uint4*)(smem + off2) = make_uint4(0, 0, 0, 0);
                *(uint4*)(smem + SLAB_BYTES + off2) = make_uint4(0, 0, 0, 0);
            }
            // first 16B half (ic 0..7)
            unsigned off = r * 32 + (((r >> 2) & 1) << 4);
            *(uint4*)(smem + off) = make_uint4(hh[0], hh[1], hh[2], hh[3]);
            *(uint4*)(smem + SLAB_BYTES + off) = make_uint4(ll[0], ll[1], ll[2], ll[3]);
        }
        __syncthreads();

        // ---- K loop over taps ----
        const uint4* wfb = d_wfrag + (size_t)(((b * 4 + g) * 27) * 256) + lane;
        #pragma unroll 1
        for (int tap = 0; tap < 27; tap++) {
            const int dt2 = tap / 9;
            const int rem = tap - dt2 * 9;
            const int dh  = rem / 3;
            const int dw  = rem - dh * 3;
            const int shift = (dt2 * HP + dh) * WP + dw;

            // B fragments: xh and xl, 48 px = 3 ldmatrix.x4 each
            unsigned bh[12], bl[12];
            #pragma unroll
            for (int q = 0; q < 3; q++) {
                int r = wid * 48 + q * 16 + rb_off + shift;
                unsigned a = r * 32 + (((((r >> 2) & 1) ^ bhalf)) << 4);
                ldmx4(bh[q * 4], bh[q * 4 + 1], bh[q * 4 + 2], bh[q * 4 + 3],
                      sl_h + a);
                ldmx4(bl[q * 4], bl[q * 4 + 1], bl[q * 4 + 2], bl[q * 4 + 3],
                      sl_l + a);
            }
            // W fragments
            const uint4* wt = wfb + tap * 256;
            uint4 wh[4], wl[4];
            #pragma unroll
            for (int mt = 0; mt < 4; mt++) {
                wh[mt] = __ldg(wt + mt * 32);
                wl[mt] = __ldg(wt + 128 + mt * 32);
            }
            // mma: acc += wh*xh + wh*xl + wl*xh
            #pragma unroll
            for (int mt = 0; mt < 4; mt++) {
                #pragma unroll
                for (int nt = 0; nt < 6; nt++) {
                    const int q = nt >> 1, pr = (nt & 1) * 2;
                    mma_bf16(acc[mt][nt], wh[mt], bh[q * 4 + pr], bh[q * 4 + pr + 1]);
                    mma_bf16(acc[mt][nt], wh[mt], bl[q * 4 + pr], bl[q * 4 + pr + 1]);
                    mma_bf16(acc[mt][nt], wl[mt], bh[q * 4 + pr], bh[q * 4 + pr + 1]);
                }
            }
        }
    }

    // ---- epilogue: c-frag rows = oc, cols = pixels (warp's h row = wid) ----
    const int gh = h0 + wid;
    #pragma unroll
    for (int mt = 0; mt < 4; mt++) {
        const int oc0 = mt * 16 + (lane >> 2);
        #pragma unroll
        for (int nt = 0; nt < 6; nt++) {
            const int wc = nt * 8 + 2 * (lane & 3);
            if (wc < W_) {
                size_t o0 = ((size_t)(b * C_ + oc0) * T_ + t) * TH_STRIDE +
                            gh * W_ + wc;
                size_t o1 = o0 + (size_t)8 * SPAT;   // oc0+8
                *(float2*)(out + o0) = make_float2(acc[mt][nt][0], acc[mt][nt][1]);
                *(float2*)(out + o1) = make_float2(acc[mt][nt][2], acc[mt][nt][3]);
            }
        }
    }
}

// ---------------------------------------------------------------------------
extern "C" void kernel_launch(void* const* d_in, const int* in_sizes, int n_in,
                              void* d_out, int out_size) {
    const float* x        = (const float*)d_in[0];
    const float* w_reduce = (const float*)d_in[1];
    const float* b_reduce = (const float*)d_in[2];
    const float* w_fc1    = (const float*)d_in[3];
    const float* b_fc1    = (const float*)d_in[4];
    const float* w_fc2    = (const float*)d_in[5];
    float* out = (float*)d_out;

    static bool attr_set = false;
    if (!attr_set) {
        cudaFuncSetAttribute(conv_kernel,
                             cudaFuncAttributeMaxDynamicSharedMemorySize, SM_TOTAL);
        attr_set = true;
    }

    gap_kernel<<<B_ * C_, 256>>>(x);
    fc_kernel<<<1, 256>>>(w_reduce, b_reduce, w_fc1, b_fc1);
    {
        const int total = B_ * 4 * 27 * 2 * 4 * 32;
        wdyn_kernel<<<(total + 255) / 256, 256>>>(w_fc2);
    }
    {
        dim3 grid(T_, H_ / HH, B_);   // (30, 8, 16)
        conv_kernel<<<grid, 256, SM_TOTAL>>>(x, out);
    }
}

// round 7
// speedup vs baseline: 5.7145x; 1.0133x over previous
#include <cuda_runtime.h>
#include <cuda_bf16.h>
#include <cstdint>
#include <cstddef>

// ---------------------------------------------------------------------------
// Problem constants
// ---------------------------------------------------------------------------
#define B_   16
#define C_   64
#define T_   30
#define H_   64
#define W_   44
#define SPAT (T_ * H_ * W_)        // 84480
#define TH_STRIDE (H_ * W_)        // 2816

// conv tiling
#define HH 8                       // output h rows per block
#define HP 10                      // h rows incl halo
#define WP 48                      // padded w per row (j = gw+1, gw in [-1,46])
#define ROWS (3 * HP * WP)         // 1440 pixel rows per slab
#define ROWSP 1456                 // padded rows: ldmatrix tap-shift bleed (max r=1441)
#define SLABB (ROWSP * 32)         // 46592 B per term slab
#define BUFB  (2 * SLABB)          // 93184 B per buffer (xh + xl)
#define SM_TOTAL (2 * BUFB)        // 186368 B (double buffered)

#define PR_ROWS (B_ * 4 * T_ * H_ * WP)   // 5,898,240 scratch rows

// Scratch (static device globals; no allocation)
__device__ float d_gap[B_ * C_];
__device__ float d_h[B_ * 128];
// W fragments, mma-lane order: [b][g:4][tap:27][term:2][mt:4][lane:32] uint4
__device__ uint4 d_wfrag[B_ * 4 * 27 * 2 * 4 * 32];
// x hi/lo bf16 scratch, smem-row layout: [b][g][t][h][j:48] rows of 32B (16 ic)
__device__ uint4 d_xh[PR_ROWS * 2];
__device__ uint4 d_xl[PR_ROWS * 2];

// ---------------------------------------------------------------------------
// helpers
// ---------------------------------------------------------------------------
__device__ __forceinline__ unsigned smem_u32(const void* p) {
    unsigned a;
    asm("{ .reg .u64 t; cvta.to.shared.u64 t, %1; cvt.u32.u64 %0, t; }"
        : "=r"(a) : "l"(p));
    return a;
}
__device__ __forceinline__ void ldmx4(unsigned& r0, unsigned& r1,
                                      unsigned& r2, unsigned& r3, unsigned a) {
    asm volatile("ldmatrix.sync.aligned.m8n8.x4.shared.b16 {%0,%1,%2,%3}, [%4];"
                 : "=r"(r0), "=r"(r1), "=r"(r2), "=r"(r3) : "r"(a));
}
__device__ __forceinline__ void mma_bf16(float* c, const uint4 a,
                                         unsigned b0, unsigned b1) {
    asm volatile(
        "mma.sync.aligned.m16n8k16.row.col.f32.bf16.bf16.f32 "
        "{%0,%1,%2,%3}, {%4,%5,%6,%7}, {%8,%9}, {%0,%1,%2,%3};"
        : "+f"(c[0]), "+f"(c[1]), "+f"(c[2]), "+f"(c[3])
        : "r"(a.x), "r"(a.y), "r"(a.z), "r"(a.w), "r"(b0), "r"(b1));
}
__device__ __forceinline__ unsigned bf_hi(float v) {
    return (unsigned)__bfloat16_as_ushort(__float2bfloat16_rn(v));
}
__device__ __forceinline__ unsigned bf_lo(float v) {
    float hf = __bfloat162float(__float2bfloat16_rn(v));
    return (unsigned)__bfloat16_as_ushort(__float2bfloat16_rn(v - hf));
}
__device__ __forceinline__ void cp16(unsigned dst, const void* src, unsigned sz) {
    asm volatile("cp.async.cg.shared.global [%0], [%1], 16, %2;"
                 :: "r"(dst), "l"(src), "r"(sz) : "memory");
}
__device__ __forceinline__ void cp_commit() {
    asm volatile("cp.async.commit_group;" ::: "memory");
}
__device__ __forceinline__ void cp_wait0() {
    asm volatile("cp.async.wait_group 0;" ::: "memory");
}

// ---------------------------------------------------------------------------
// Kernel 1: global average pool. 1024 blocks.
// ---------------------------------------------------------------------------
__global__ void gap_kernel(const float* __restrict__ x) {
    const int bc = blockIdx.x;
    const float4* xp = reinterpret_cast<const float4*>(x) + (size_t)bc * (SPAT / 4);
    float s = 0.f;
    for (int i = threadIdx.x; i < SPAT / 4; i += 256) {
        float4 v = xp[i];
        s += (v.x + v.y) + (v.z + v.w);
    }
    #pragma unroll
    for (int o = 16; o > 0; o >>= 1) s += __shfl_xor_sync(0xffffffffu, s, o);
    __shared__ float red[8];
    if ((threadIdx.x & 31) == 0) red[threadIdx.x >> 5] = s;
    __syncthreads();
    if (threadIdx.x < 8) {
        float v = red[threadIdx.x];
        #pragma unroll
        for (int o = 4; o > 0; o >>= 1) v += __shfl_xor_sync(0xffu, v, o);
        if (threadIdx.x == 0) d_gap[bc] = v * (1.0f / (float)SPAT);
    }
}

// ---------------------------------------------------------------------------
// Kernel 2: reduce FC + fc1 + sigmoid. Single block.
// ---------------------------------------------------------------------------
__global__ void fc_kernel(const float* __restrict__ w_reduce,
                          const float* __restrict__ b_reduce,
                          const float* __restrict__ w_fc1,
                          const float* __restrict__ b_fc1) {
    __shared__ float sg[B_ * 16];
    const int tid = threadIdx.x;
    if (tid < B_ * 16) {
        int b = tid >> 4, j = tid & 15;
        float s = b_reduce[j];
        #pragma unroll 4
        for (int i = 0; i < 64; i++) s += d_gap[b * 64 + i] * w_reduce[j * 64 + i];
        sg[b * 16 + j] = s;
    }
    __syncthreads();
    for (int idx = tid; idx < B_ * 128; idx += 256) {
        int b = idx >> 7, c = idx & 127;
        float s = b_fc1[c];
        #pragma unroll
        for (int i = 0; i < 16; i++) s += sg[b * 16 + i] * w_fc1[c * 16 + i];
        d_h[idx] = 1.0f / (1.0f + expf(-s));
    }
}

// ---------------------------------------------------------------------------
// Kernel 3: dynamic weights -> mma a-fragment layout (hi and lo terms).
// ---------------------------------------------------------------------------
__global__ void wdyn_kernel(const float* __restrict__ w_fc2) {
    const int idx = blockIdx.x * blockDim.x + threadIdx.x;
    const int total = B_ * 4 * 27 * 2 * 4 * 32;   // 442368
    if (idx >= total) return;
    const int lane = idx & 31;
    const int mt   = (idx >> 5) & 3;
    const int term = (idx >> 7) & 1;
    int q = idx >> 8;
    const int tap = q % 27;  q /= 27;
    const int g   = q & 3;
    const int b   = q >> 2;

    unsigned r32[4];
    #pragma unroll
    for (int r = 0; r < 4; r++) {
        const int row = (lane >> 2) + (r & 1) * 8;
        const int kb  = 2 * (lane & 3) + (r >> 1) * 8;
        const int oc  = mt * 16 + row;
        unsigned e[2];
        #pragma unroll
        for (int j = 0; j < 2; j++) {
            const int ic = g * 16 + kb + j;
            const float v = w_fc2[oc * 1728 + ic * 27 + tap] *
                            d_h[b * 128 + oc * 2 + (ic >= 32 ? 1 : 0)];
            e[j] = term == 0 ? bf_hi(v) : bf_lo(v);
        }
        r32[r] = e[0] | (e[1] << 16);
    }
    d_wfrag[idx] = make_uint4(r32[0], r32[1], r32[2], r32[3]);
}

// ---------------------------------------------------------------------------
// Kernel 3b: x pre-pass. One thread per scratch row (b,g,t,h,j):
// converts 16 ic f32 -> bf16 hi/lo, writes two 16B halves. W-halo pre-zeroed.
// ---------------------------------------------------------------------------
__global__ void prepass_kernel(const float* __restrict__ x) {
    const int i = blockIdx.x * 256 + threadIdx.x;
    if (i >= PR_ROWS) return;
    int j = i % WP;  int q = i / WP;
    int h = q % H_;  q /= H_;
    int t = q % T_;  q /= T_;
    int g = q & 3;
    int b = q >> 2;

    uint4 h0 = make_uint4(0, 0, 0, 0), h1 = h0, l0 = h0, l1 = h0;
    const int gw = j - 1;
    if ((unsigned)gw < (unsigned)W_) {
        const float* p = x + ((size_t)(b * C_ + g * 16) * T_ + t) * TH_STRIDE +
                         h * W_ + gw;
        unsigned hh[8], ll[8];
        #pragma unroll
        for (int k = 0; k < 8; k++) {
            float v0 = __ldg(p + (size_t)(2 * k) * SPAT);
            float v1 = __ldg(p + (size_t)(2 * k + 1) * SPAT);
            hh[k] = bf_hi(v0) | (bf_hi(v1) << 16);
            ll[k] = bf_lo(v0) | (bf_lo(v1) << 16);
        }
        h0 = make_uint4(hh[0], hh[1], hh[2], hh[3]);
        h1 = make_uint4(hh[4], hh[5], hh[6], hh[7]);
        l0 = make_uint4(ll[0], ll[1], ll[2], ll[3]);
        l1 = make_uint4(ll[4], ll[5], ll[6], ll[7]);
    }
    d_xh[(size_t)i * 2]     = h0;
    d_xh[(size_t)i * 2 + 1] = h1;
    d_xl[(size_t)i * 2]     = l0;
    d_xl[(size_t)i * 2 + 1] = l1;
}

// ---------------------------------------------------------------------------
// Kernel 4: implicit-GEMM conv via mma.sync bf16 (3-term hi/lo split),
// cp.async double-buffered A slabs from pre-converted scratch.
// Block = (t, hgroup of 8, b); 8 warps, warp = m64(oc) x n48(one h row).
// ---------------------------------------------------------------------------
extern __shared__ char smem[];

__global__ void __launch_bounds__(256, 1)
conv_kernel(float* __restrict__ out) {
    const int t  = blockIdx.x;
    const int h0 = blockIdx.y * HH;
    const int b  = blockIdx.z;
    const int tid = threadIdx.x;
    const int wid = tid >> 5;
    const int lane = tid & 31;

    const unsigned sb = smem_u32(smem);

    float acc[4][6][4];
    #pragma unroll
    for (int mt = 0; mt < 4; mt++)
        #pragma unroll
        for (int nt = 0; nt < 6; nt++)
            #pragma unroll
            for (int k = 0; k < 4; k++) acc[mt][nt][k] = 0.f;

    // ldmatrix lane address components
    const int rb_off = (lane & 7) + ((lane >> 4) & 1) * 8;
    const int bhalf  = (lane >> 3) & 1;

    // ---- prefetch: fill buffer `buf` with group `g` slabs (zfill halo) ----
    auto prefetch = [&](int g, int buf) {
        const char* xh8 = reinterpret_cast<const char*>(d_xh);
        const char* xl8 = reinterpret_cast<const char*>(d_xl);
        #pragma unroll 1
        for (int i = tid; i < 2 * ROWS * 2; i += 256) {   // 5760 16B ops
            const int term = i >= 2 * ROWS;
            const int rem  = term ? i - 2 * ROWS : i;
            const int r  = rem >> 1;
            const int hb = rem & 1;
            int t2 = r / (HP * WP);
            int rr = r - t2 * (HP * WP);
            int hp = rr / WP;
            int wp = rr - hp * WP;
            const int gt = t + t2 - 1, gh = h0 + hp - 1;
            const unsigned ok =
                (((unsigned)gt < (unsigned)T_) & ((unsigned)gh < (unsigned)H_))
                ? 16u : 0u;
            const int gtc = gt < 0 ? 0 : (gt >= T_ ? T_ - 1 : gt);
            const int ghc = gh < 0 ? 0 : (gh >= H_ ? H_ - 1 : gh);
            const size_t srow =
                ((((size_t)(b * 4 + g) * T_ + gtc) * H_ + ghc) * WP + wp);
            const char* src = (term ? xl8 : xh8) + srow * 32 + hb * 16;
            const unsigned dst = sb + buf * BUFB + term * SLABB + r * 32 +
                                 ((((r >> 2) & 1) ^ hb) << 4);
            cp16(dst, src, ok);
        }
        cp_commit();
    };

    prefetch(0, 0);

    #pragma unroll 1
    for (int g = 0; g < 4; g++) {
        cp_wait0();
        __syncthreads();
        if (g < 3) prefetch(g + 1, (g + 1) & 1);

        const unsigned sl_h = sb + (g & 1) * BUFB;
        const unsigned sl_l = sl_h + SLABB;

        const uint4* wfb = d_wfrag + (size_t)(((b * 4 + g) * 27) * 256) + lane;
        #pragma unroll 1
        for (int tap = 0; tap < 27; tap++) {
            const int dt2 = tap / 9;
            const int rem = tap - dt2 * 9;
            const int dh  = rem / 3;
            const int dw  = rem - dh * 3;
            const int shift = (dt2 * HP + dh) * WP + dw;

            unsigned bh[12], bl[12];
            #pragma unroll
            for (int q = 0; q < 3; q++) {
                int r = wid * 48 + q * 16 + rb_off + shift;
                unsigned a = r * 32 + (((((r >> 2) & 1) ^ bhalf)) << 4);
                ldmx4(bh[q * 4], bh[q * 4 + 1], bh[q * 4 + 2], bh[q * 4 + 3],
                      sl_h + a);
                ldmx4(bl[q * 4], bl[q * 4 + 1], bl[q * 4 + 2], bl[q * 4 + 3],
                      sl_l + a);
            }
            const uint4* wt = wfb + tap * 256;
            uint4 wh[4], wl[4];
            #pragma unroll
            for (int mt = 0; mt < 4; mt++) {
                wh[mt] = __ldg(wt + mt * 32);
                wl[mt] = __ldg(wt + 128 + mt * 32);
            }
            #pragma unroll
            for (int mt = 0; mt < 4; mt++) {
                #pragma unroll
                for (int nt = 0; nt < 6; nt++) {
                    const int q = nt >> 1, pr = (nt & 1) * 2;
                    mma_bf16(acc[mt][nt], wh[mt], bh[q * 4 + pr], bh[q * 4 + pr + 1]);
                    mma_bf16(acc[mt][nt], wh[mt], bl[q * 4 + pr], bl[q * 4 + pr + 1]);
                    mma_bf16(acc[mt][nt], wl[mt], bh[q * 4 + pr], bh[q * 4 + pr + 1]);
                }
            }
        }
    }

    // ---- epilogue ----
    const int gh = h0 + wid;
    #pragma unroll
    for (int mt = 0; mt < 4; mt++) {
        const int oc0 = mt * 16 + (lane >> 2);
        #pragma unroll
        for (int nt = 0; nt < 6; nt++) {
            const int wc = nt * 8 + 2 * (lane & 3);
            if (wc < W_) {
                size_t o0 = ((size_t)(b * C_ + oc0) * T_ + t) * TH_STRIDE +
                            gh * W_ + wc;
                size_t o1 = o0 + (size_t)8 * SPAT;
                *(float2*)(out + o0) = make_float2(acc[mt][nt][0], acc[mt][nt][1]);
                *(float2*)(out + o1) = make_float2(acc[mt][nt][2], acc[mt][nt][3]);
            }
        }
    }
}

// ---------------------------------------------------------------------------
extern "C" void kernel_launch(void* const* d_in, const int* in_sizes, int n_in,
                              void* d_out, int out_size) {
    const float* x        = (const float*)d_in[0];
    const float* w_reduce = (const float*)d_in[1];
    const float* b_reduce = (const float*)d_in[2];
    const float* w_fc1    = (const float*)d_in[3];
    const float* b_fc1    = (const float*)d_in[4];
    const float* w_fc2    = (const float*)d_in[5];
    float* out = (float*)d_out;

    cudaFuncSetAttribute(conv_kernel,
                         cudaFuncAttributeMaxDynamicSharedMemorySize, SM_TOTAL);

    gap_kernel<<<B_ * C_, 256>>>(x);
    fc_kernel<<<1, 256>>>(w_reduce, b_reduce, w_fc1, b_fc1);
    {
        const int total = B_ * 4 * 27 * 2 * 4 * 32;
        wdyn_kernel<<<(total + 255) / 256, 256>>>(w_fc2);
    }
    prepass_kernel<<<(PR_ROWS + 255) / 256, 256>>>(x);
    {
        dim3 grid(T_, H_ / HH, B_);   // (30, 8, 16)
        conv_kernel<<<grid, 256, SM_TOTAL>>>(out);
    }
}

// round 8
// speedup vs baseline: 6.0137x; 1.0524x over previous
#include <cuda_runtime.h>
#include <cuda_bf16.h>
#include <cstdint>
#include <cstddef>

// ---------------------------------------------------------------------------
// Problem constants
// ---------------------------------------------------------------------------
#define B_   16
#define C_   64
#define T_   30
#define H_   64
#define W_   44
#define SPAT (T_ * H_ * W_)        // 84480
#define TH_STRIDE (H_ * W_)        // 2816

// conv tiling
#define HH 8                       // output h rows per block
#define HP 10                      // h rows incl halo
#define WP 48                      // padded w per row (j = gw+1, gw in [-1,46])
#define ROWS (3 * HP * WP)         // 1440 pixel rows per slab
#define ROWSP 1456                 // padded rows: ldmatrix tap-shift bleed (max r=1441)
#define SLABB (ROWSP * 32)         // 46592 B per term slab
#define BUFB  (2 * SLABB)          // 93184 B per buffer (xh + xl)
#define SM_TOTAL (2 * BUFB)        // 186368 B (double buffered)

#define PR_ROWS (B_ * 4 * T_ * H_ * WP)   // 5,898,240 scratch rows

// Scratch (static device globals; no allocation)
__device__ float d_gap[B_ * C_];
__device__ float d_h[B_ * 128];
// W fragments, mma-lane order: [b][g:4][tap:27][term:2][mt:4][lane:32] uint4
__device__ uint4 d_wfrag[B_ * 4 * 27 * 2 * 4 * 32];
// x hi/lo bf16 scratch, smem-row layout: [b][g][t][h][j:48] rows of 32B (16 ic)
__device__ uint4 d_xh[PR_ROWS * 2];
__device__ uint4 d_xl[PR_ROWS * 2];

// ---------------------------------------------------------------------------
// helpers
// ---------------------------------------------------------------------------
__device__ __forceinline__ unsigned smem_u32(const void* p) {
    unsigned a;
    asm("{ .reg .u64 t; cvta.to.shared.u64 t, %1; cvt.u32.u64 %0, t; }"
        : "=r"(a) : "l"(p));
    return a;
}
__device__ __forceinline__ void ldmx4(unsigned& r0, unsigned& r1,
                                      unsigned& r2, unsigned& r3, unsigned a) {
    asm volatile("ldmatrix.sync.aligned.m8n8.x4.shared.b16 {%0,%1,%2,%3}, [%4];"
                 : "=r"(r0), "=r"(r1), "=r"(r2), "=r"(r3) : "r"(a));
}
__device__ __forceinline__ void mma_bf16(float* c, const uint4 a,
                                         unsigned b0, unsigned b1) {
    asm volatile(
        "mma.sync.aligned.m16n8k16.row.col.f32.bf16.bf16.f32 "
        "{%0,%1,%2,%3}, {%4,%5,%6,%7}, {%8,%9}, {%0,%1,%2,%3};"
        : "+f"(c[0]), "+f"(c[1]), "+f"(c[2]), "+f"(c[3])
        : "r"(a.x), "r"(a.y), "r"(a.z), "r"(a.w), "r"(b0), "r"(b1));
}
__device__ __forceinline__ unsigned bf_hi(float v) {
    return (unsigned)__bfloat16_as_ushort(__float2bfloat16_rn(v));
}
__device__ __forceinline__ unsigned bf_lo(float v) {
    float hf = __bfloat162float(__float2bfloat16_rn(v));
    return (unsigned)__bfloat16_as_ushort(__float2bfloat16_rn(v - hf));
}
__device__ __forceinline__ void cp16(unsigned dst, const void* src, unsigned sz) {
    asm volatile("cp.async.cg.shared.global [%0], [%1], 16, %2;"
                 :: "r"(dst), "l"(src), "r"(sz) : "memory");
}
__device__ __forceinline__ void cp_commit() {
    asm volatile("cp.async.commit_group;" ::: "memory");
}
__device__ __forceinline__ void cp_wait0() {
    asm volatile("cp.async.wait_group 0;" ::: "memory");
}

// ---------------------------------------------------------------------------
// Kernel 1: global average pool. 1024 blocks.
// ---------------------------------------------------------------------------
__global__ void gap_kernel(const float* __restrict__ x) {
    const int bc = blockIdx.x;
    const float4* xp = reinterpret_cast<const float4*>(x) + (size_t)bc * (SPAT / 4);
    float s = 0.f;
    for (int i = threadIdx.x; i < SPAT / 4; i += 256) {
        float4 v = xp[i];
        s += (v.x + v.y) + (v.z + v.w);
    }
    #pragma unroll
    for (int o = 16; o > 0; o >>= 1) s += __shfl_xor_sync(0xffffffffu, s, o);
    __shared__ float red[8];
    if ((threadIdx.x & 31) == 0) red[threadIdx.x >> 5] = s;
    __syncthreads();
    if (threadIdx.x < 8) {
        float v = red[threadIdx.x];
        #pragma unroll
        for (int o = 4; o > 0; o >>= 1) v += __shfl_xor_sync(0xffu, v, o);
        if (threadIdx.x == 0) d_gap[bc] = v * (1.0f / (float)SPAT);
    }
}

// ---------------------------------------------------------------------------
// Kernel 2: reduce FC + fc1 + sigmoid. Single block.
// ---------------------------------------------------------------------------
__global__ void fc_kernel(const float* __restrict__ w_reduce,
                          const float* __restrict__ b_reduce,
                          const float* __restrict__ w_fc1,
                          const float* __restrict__ b_fc1) {
    __shared__ float sg[B_ * 16];
    const int tid = threadIdx.x;
    if (tid < B_ * 16) {
        int b = tid >> 4, j = tid & 15;
        float s = b_reduce[j];
        #pragma unroll 4
        for (int i = 0; i < 64; i++) s += d_gap[b * 64 + i] * w_reduce[j * 64 + i];
        sg[b * 16 + j] = s;
    }
    __syncthreads();
    for (int idx = tid; idx < B_ * 128; idx += 256) {
        int b = idx >> 7, c = idx & 127;
        float s = b_fc1[c];
        #pragma unroll
        for (int i = 0; i < 16; i++) s += sg[b * 16 + i] * w_fc1[c * 16 + i];
        d_h[idx] = 1.0f / (1.0f + expf(-s));
    }
}

// ---------------------------------------------------------------------------
// Kernel 3: dynamic weights -> mma a-fragment layout (hi and lo terms).
// ---------------------------------------------------------------------------
__global__ void wdyn_kernel(const float* __restrict__ w_fc2) {
    const int idx = blockIdx.x * blockDim.x + threadIdx.x;
    const int total = B_ * 4 * 27 * 2 * 4 * 32;   // 442368
    if (idx >= total) return;
    const int lane = idx & 31;
    const int mt   = (idx >> 5) & 3;
    const int term = (idx >> 7) & 1;
    int q = idx >> 8;
    const int tap = q % 27;  q /= 27;
    const int g   = q & 3;
    const int b   = q >> 2;

    unsigned r32[4];
    #pragma unroll
    for (int r = 0; r < 4; r++) {
        const int row = (lane >> 2) + (r & 1) * 8;
        const int kb  = 2 * (lane & 3) + (r >> 1) * 8;
        const int oc  = mt * 16 + row;
        unsigned e[2];
        #pragma unroll
        for (int j = 0; j < 2; j++) {
            const int ic = g * 16 + kb + j;
            const float v = w_fc2[oc * 1728 + ic * 27 + tap] *
                            d_h[b * 128 + oc * 2 + (ic >= 32 ? 1 : 0)];
            e[j] = term == 0 ? bf_hi(v) : bf_lo(v);
        }
        r32[r] = e[0] | (e[1] << 16);
    }
    d_wfrag[idx] = make_uint4(r32[0], r32[1], r32[2], r32[3]);
}

// ---------------------------------------------------------------------------
// Kernel 3b: x pre-pass. One thread per scratch row (b,g,t,h,j):
// converts 16 ic f32 -> bf16 hi/lo, writes two 16B halves. W-halo pre-zeroed.
// ---------------------------------------------------------------------------
__global__ void prepass_kernel(const float* __restrict__ x) {
    const int i = blockIdx.x * 256 + threadIdx.x;
    if (i >= PR_ROWS) return;
    int j = i % WP;  int q = i / WP;
    int h = q % H_;  q /= H_;
    int t = q % T_;  q /= T_;
    int g = q & 3;
    int b = q >> 2;

    uint4 h0 = make_uint4(0, 0, 0, 0), h1 = h0, l0 = h0, l1 = h0;
    const int gw = j - 1;
    if ((unsigned)gw < (unsigned)W_) {
        const float* p = x + ((size_t)(b * C_ + g * 16) * T_ + t) * TH_STRIDE +
                         h * W_ + gw;
        unsigned hh[8], ll[8];
        #pragma unroll
        for (int k = 0; k < 8; k++) {
            float v0 = __ldg(p + (size_t)(2 * k) * SPAT);
            float v1 = __ldg(p + (size_t)(2 * k + 1) * SPAT);
            hh[k] = bf_hi(v0) | (bf_hi(v1) << 16);
            ll[k] = bf_lo(v0) | (bf_lo(v1) << 16);
        }
        h0 = make_uint4(hh[0], hh[1], hh[2], hh[3]);
        h1 = make_uint4(hh[4], hh[5], hh[6], hh[7]);
        l0 = make_uint4(ll[0], ll[1], ll[2], ll[3]);
        l1 = make_uint4(ll[4], ll[5], ll[6], ll[7]);
    }
    d_xh[(size_t)i * 2]     = h0;
    d_xh[(size_t)i * 2 + 1] = h1;
    d_xl[(size_t)i * 2]     = l0;
    d_xl[(size_t)i * 2 + 1] = l1;
}

// ---------------------------------------------------------------------------
// Kernel 4: implicit-GEMM conv via mma.sync bf16 (3-term hi/lo split).
// cp.async double-buffered A slabs + W-fragment LDG pipelined one tap ahead.
// Block = (t, hgroup of 8, b); 8 warps, warp = m64(oc) x n48(one h row).
// ---------------------------------------------------------------------------
extern __shared__ char smem[];

__global__ void __launch_bounds__(256, 1)
conv_kernel(float* __restrict__ out) {
    const int t  = blockIdx.x;
    const int h0 = blockIdx.y * HH;
    const int b  = blockIdx.z;
    const int tid = threadIdx.x;
    const int wid = tid >> 5;
    const int lane = tid & 31;

    const unsigned sb = smem_u32(smem);

    float acc[4][6][4];
    #pragma unroll
    for (int mt = 0; mt < 4; mt++)
        #pragma unroll
        for (int nt = 0; nt < 6; nt++)
            #pragma unroll
            for (int k = 0; k < 4; k++) acc[mt][nt][k] = 0.f;

    // ldmatrix lane address components
    const int rb_off = (lane & 7) + ((lane >> 4) & 1) * 8;
    const int bhalf  = (lane >> 3) & 1;

    // ---- prefetch: fill buffer `buf` with group `g` slabs (zfill halo) ----
    auto prefetch = [&](int g, int buf) {
        const char* xh8 = reinterpret_cast<const char*>(d_xh);
        const char* xl8 = reinterpret_cast<const char*>(d_xl);
        #pragma unroll 1
        for (int i = tid; i < 2 * ROWS * 2; i += 256) {   // 5760 16B ops
            const int term = i >= 2 * ROWS;
            const int rem  = term ? i - 2 * ROWS : i;
            const int r  = rem >> 1;
            const int hb = rem & 1;
            int t2 = r / (HP * WP);
            int rr = r - t2 * (HP * WP);
            int hp = rr / WP;
            int wp = rr - hp * WP;
            const int gt = t + t2 - 1, gh = h0 + hp - 1;
            const unsigned ok =
                (((unsigned)gt < (unsigned)T_) & ((unsigned)gh < (unsigned)H_))
                ? 16u : 0u;
            const int gtc = gt < 0 ? 0 : (gt >= T_ ? T_ - 1 : gt);
            const int ghc = gh < 0 ? 0 : (gh >= H_ ? H_ - 1 : gh);
            const size_t srow =
                ((((size_t)(b * 4 + g) * T_ + gtc) * H_ + ghc) * WP + wp);
            const char* src = (term ? xl8 : xh8) + srow * 32 + hb * 16;
            const unsigned dst = sb + buf * BUFB + term * SLABB + r * 32 +
                                 ((((r >> 2) & 1) ^ hb) << 4);
            cp16(dst, src, ok);
        }
        cp_commit();
    };

    prefetch(0, 0);

    // W-fragment pointer for flat k = g*27 + tap (clamped at the end)
    const uint4* wf0 = d_wfrag + (size_t)(b * 4) * 27 * 256 + lane;
    auto wptr = [&](int k) { return wf0 + (size_t)k * 256; };

    // preload W fragments for k = 0
    uint4 whc[4], wlc[4];
    {
        const uint4* wt = wptr(0);
        #pragma unroll
        for (int mt = 0; mt < 4; mt++) {
            whc[mt] = __ldg(wt + mt * 32);
            wlc[mt] = __ldg(wt + 128 + mt * 32);
        }
    }

    #pragma unroll 1
    for (int g = 0; g < 4; g++) {
        cp_wait0();
        __syncthreads();
        if (g < 3) prefetch(g + 1, (g + 1) & 1);

        const unsigned sl_h = sb + (g & 1) * BUFB;
        const unsigned sl_l = sl_h + SLABB;

        #pragma unroll 1
        for (int tap = 0; tap < 27; tap++) {
            // ---- prefetch next tap's W fragments (one tap / g ahead) ----
            const int kf = g * 27 + tap;
            const uint4* wt = wptr(kf < 107 ? kf + 1 : 107);
            uint4 whn[4], wln[4];
            #pragma unroll
            for (int mt = 0; mt < 4; mt++) {
                whn[mt] = __ldg(wt + mt * 32);
                wln[mt] = __ldg(wt + 128 + mt * 32);
            }

            // ---- B fragments for current tap ----
            const int dt2 = tap / 9;
            const int rem = tap - dt2 * 9;
            const int dh  = rem / 3;
            const int dw  = rem - dh * 3;
            const int shift = (dt2 * HP + dh) * WP + dw;

            unsigned bh[12], bl[12];
            #pragma unroll
            for (int q = 0; q < 3; q++) {
                int r = wid * 48 + q * 16 + rb_off + shift;
                unsigned a = r * 32 + (((((r >> 2) & 1) ^ bhalf)) << 4);
                ldmx4(bh[q * 4], bh[q * 4 + 1], bh[q * 4 + 2], bh[q * 4 + 3],
                      sl_h + a);
                ldmx4(bl[q * 4], bl[q * 4 + 1], bl[q * 4 + 2], bl[q * 4 + 3],
                      sl_l + a);
            }

            // ---- mma with current (preloaded) W fragments ----
            #pragma unroll
            for (int mt = 0; mt < 4; mt++) {
                #pragma unroll
                for (int nt = 0; nt < 6; nt++) {
                    const int q = nt >> 1, pr = (nt & 1) * 2;
                    mma_bf16(acc[mt][nt], whc[mt], bh[q * 4 + pr], bh[q * 4 + pr + 1]);
                    mma_bf16(acc[mt][nt], whc[mt], bl[q * 4 + pr], bl[q * 4 + pr + 1]);
                    mma_bf16(acc[mt][nt], wlc[mt], bh[q * 4 + pr], bh[q * 4 + pr + 1]);
                }
            }

            // ---- rotate pipeline ----
            #pragma unroll
            for (int mt = 0; mt < 4; mt++) {
                whc[mt] = whn[mt];
                wlc[mt] = wln[mt];
            }
        }
    }

    // ---- epilogue ----
    const int gh = h0 + wid;
    #pragma unroll
    for (int mt = 0; mt < 4; mt++) {
        const int oc0 = mt * 16 + (lane >> 2);
        #pragma unroll
        for (int nt = 0; nt < 6; nt++) {
            const int wc = nt * 8 + 2 * (lane & 3);
            if (wc < W_) {
                size_t o0 = ((size_t)(b * C_ + oc0) * T_ + t) * TH_STRIDE +
                            gh * W_ + wc;
                size_t o1 = o0 + (size_t)8 * SPAT;
                *(float2*)(out + o0) = make_float2(acc[mt][nt][0], acc[mt][nt][1]);
                *(float2*)(out + o1) = make_float2(acc[mt][nt][2], acc[mt][nt][3]);
            }
        }
    }
}

// ---------------------------------------------------------------------------
extern "C" void kernel_launch(void* const* d_in, const int* in_sizes, int n_in,
                              void* d_out, int out_size) {
    const float* x        = (const float*)d_in[0];
    const float* w_reduce = (const float*)d_in[1];
    const float* b_reduce = (const float*)d_in[2];
    const float* w_fc1    = (const float*)d_in[3];
    const float* b_fc1    = (const float*)d_in[4];
    const float* w_fc2    = (const float*)d_in[5];
    float* out = (float*)d_out;

    cudaFuncSetAttribute(conv_kernel,
                         cudaFuncAttributeMaxDynamicSharedMemorySize, SM_TOTAL);

    gap_kernel<<<B_ * C_, 256>>>(x);
    fc_kernel<<<1, 256>>>(w_reduce, b_reduce, w_fc1, b_fc1);
    {
        const int total = B_ * 4 * 27 * 2 * 4 * 32;
        wdyn_kernel<<<(total + 255) / 256, 256>>>(w_fc2);
    }
    prepass_kernel<<<(PR_ROWS + 255) / 256, 256>>>(x);
    {
        dim3 grid(T_, H_ / HH, B_);   // (30, 8, 16)
        conv_kernel<<<grid, 256, SM_TOTAL>>>(out);
    }
}